// round 7
// baseline (speedup 1.0000x reference)
#include <cuda_runtime.h>
#include <cuda_bf16.h>
#include <cstdint>

#define Bn 4
#define Cn 64
#define Hn 256
#define Wn 256
#define HWn (Hn * Wn)

// Scratch (sanctioned __device__ globals; no allocations anywhere)
__device__ float g_edge[Bn * HWn];                 // 1 MB
__device__ float g_wts[Bn * 4 * HWn];              // 4 MB  layout [b][k][h][w], k = |offset|
__device__ float g_tmp[(size_t)Bn * Cn * HWn];     // 64 MB horizontal-pass result
__device__ unsigned int g_minmax[2 * Bn];          // [0..3]=min bits, [4..7]=max bits

__global__ void init_minmax_kernel() {
    int i = threadIdx.x;
    if (i < Bn) {
        g_minmax[i]      = 0x7f7fffffu;  // +FLT_MAX
        g_minmax[Bn + i] = 0u;           // 0.0f (edge >= 0)
    }
}

// One block per (b,h); 256 threads = w. Loops 64 channels through a 3-row smem tile.
// Accumulates sum over channels of gx^2+gy^2, writes edge = mean, fused min/max reduce.
__global__ void edge_kernel(const float* __restrict__ x) {
    const int w = threadIdx.x;
    const int h = blockIdx.x;
    const int b = blockIdx.y;

    __shared__ float s[3][Wn + 2];

    float acc = 0.f;
    const float* xb = x + (size_t)b * Cn * HWn;

    for (int c = 0; c < Cn; ++c) {
        const float* plane = xb + (size_t)c * HWn;
        __syncthreads();
#pragma unroll
        for (int r = 0; r < 3; ++r) {
            int hh = h - 1 + r;
            s[r][w + 1] = (hh >= 0 && hh < Hn) ? plane[hh * Wn + w] : 0.f;
        }
        if (w == 0) {
#pragma unroll
            for (int r = 0; r < 3; ++r) { s[r][0] = 0.f; s[r][Wn + 1] = 0.f; }
        }
        __syncthreads();

        float t00 = s[0][w], t01 = s[0][w + 1], t02 = s[0][w + 2];
        float t10 = s[1][w],                    t12 = s[1][w + 2];
        float t20 = s[2][w], t21 = s[2][w + 1], t22 = s[2][w + 2];

        float gx = (t02 - t00) + 2.f * (t12 - t10) + (t22 - t20);
        float gy = (t20 - t00) + 2.f * (t21 - t01) + (t22 - t02);
        acc += gx * gx + gy * gy;
    }

    float e = acc * (1.f / (float)Cn);
    g_edge[(b * Hn + h) * Wn + w] = e;

    // block min/max reduction -> per-batch atomics (non-negative floats order as uints)
    float mn = e, mx = e;
#pragma unroll
    for (int o = 16; o > 0; o >>= 1) {
        mn = fminf(mn, __shfl_xor_sync(0xffffffffu, mn, o));
        mx = fmaxf(mx, __shfl_xor_sync(0xffffffffu, mx, o));
    }
    __shared__ float smn[8], smx[8];
    int lane = w & 31, wid = w >> 5;
    if (lane == 0) { smn[wid] = mn; smx[wid] = mx; }
    __syncthreads();
    if (w == 0) {
        float m1 = smn[0], m2 = smx[0];
#pragma unroll
        for (int i = 1; i < 8; ++i) { m1 = fminf(m1, smn[i]); m2 = fmaxf(m2, smx[i]); }
        atomicMin(&g_minmax[b], __float_as_uint(m1));
        atomicMax(&g_minmax[Bn + b], __float_as_uint(m2));
    }
}

// Per-pixel sigma -> 4 symmetric normalized Gaussian weight planes.
__global__ void weights_kernel() {
    int idx = blockIdx.x * blockDim.x + threadIdx.x;  // 0..HW-1
    int b   = blockIdx.y;

    float e    = g_edge[b * HWn + idx];
    float emin = __uint_as_float(g_minmax[b]);
    float emax = __uint_as_float(g_minmax[Bn + b]);
    float en   = (e - emin) / (emax + 1e-6f);
    float sig  = 0.6f + 0.6f * en;
    float inv  = 1.f / (2.f * sig * sig);

    float w1 = __expf(-inv);
    float w2 = __expf(-4.f * inv);
    float w3 = __expf(-9.f * inv);
    float r  = 1.f / (1.f + 2.f * (w1 + w2 + w3));

    float* gb = g_wts + (size_t)b * 4 * HWn + idx;
    gb[0]        = r;
    gb[HWn]      = w1 * r;
    gb[2 * HWn]  = w2 * r;
    gb[3 * HWn]  = w3 * r;
}

// Horizontal pass: block = (h, c, b), threads = w. Row + 3-wide zero halos in smem.
__global__ void hblur_kernel(const float* __restrict__ x) {
    const int w = threadIdx.x;
    const int h = blockIdx.x;
    const int c = blockIdx.y;
    const int b = blockIdx.z;

    __shared__ float row[Wn + 6];
    const float* src = x + (((size_t)(b * Cn + c)) * Hn + h) * Wn;
    row[w + 3] = src[w];
    if (w < 3)       row[w]     = 0.f;
    if (w >= Wn - 3) row[w + 6] = 0.f;
    __syncthreads();

    size_t gbase = (size_t)b * 4 * HWn + (size_t)h * Wn + w;
    float g0 = g_wts[gbase];
    float g1 = g_wts[gbase + HWn];
    float g2 = g_wts[gbase + 2 * HWn];
    float g3 = g_wts[gbase + 3 * HWn];

    float v = g0 * row[w + 3]
            + g1 * (row[w + 2] + row[w + 4])
            + g2 * (row[w + 1] + row[w + 5])
            + g3 * (row[w]     + row[w + 6]);

    g_tmp[(((size_t)(b * Cn + c)) * Hn + h) * Wn + w] = v;
}

// Vertical pass: same per-pixel weights, rows h-3..h+3 (zero OOB), coalesced along w.
__global__ void vblur_kernel(float* __restrict__ out) {
    const int w = threadIdx.x;
    const int h = blockIdx.x;
    const int c = blockIdx.y;
    const int b = blockIdx.z;

    const float* tp = g_tmp + ((size_t)(b * Cn + c)) * HWn;

    size_t gbase = (size_t)b * 4 * HWn + (size_t)h * Wn + w;
    float g0 = g_wts[gbase];
    float g1 = g_wts[gbase + HWn];
    float g2 = g_wts[gbase + 2 * HWn];
    float g3 = g_wts[gbase + 3 * HWn];

    float c0 = tp[h * Wn + w];
    float u1 = (h >= 1)      ? tp[(h - 1) * Wn + w] : 0.f;
    float d1 = (h <= Hn - 2) ? tp[(h + 1) * Wn + w] : 0.f;
    float u2 = (h >= 2)      ? tp[(h - 2) * Wn + w] : 0.f;
    float d2 = (h <= Hn - 3) ? tp[(h + 2) * Wn + w] : 0.f;
    float u3 = (h >= 3)      ? tp[(h - 3) * Wn + w] : 0.f;
    float d3 = (h <= Hn - 4) ? tp[(h + 3) * Wn + w] : 0.f;

    float v = g0 * c0 + g1 * (u1 + d1) + g2 * (u2 + d2) + g3 * (u3 + d3);
    out[(((size_t)(b * Cn + c)) * Hn + h) * Wn + w] = v;
}

extern "C" void kernel_launch(void* const* d_in, const int* in_sizes, int n_in,
                              void* d_out, int out_size) {
    const float* x = (const float*)d_in[0];
    float* out = (float*)d_out;
    (void)in_sizes; (void)n_in; (void)out_size;

    init_minmax_kernel<<<1, 32>>>();
    edge_kernel<<<dim3(Hn, Bn), Wn>>>(x);
    weights_kernel<<<dim3(HWn / 256, Bn), 256>>>();
    hblur_kernel<<<dim3(Hn, Cn, Bn), Wn>>>(x);
    vblur_kernel<<<dim3(Hn, Cn, Bn), Wn>>>(out);
}

// round 13
// speedup vs baseline: 1.5793x; 1.5793x over previous
#include <cuda_runtime.h>
#include <cuda_bf16.h>
#include <cstdint>

#define Bn 4
#define Cn 64
#define Hn 256
#define Wn 256
#define HWn (Hn * Wn)

// Edge kernel tiling
#define TE 8                 // output rows per edge block
#define ECPB 16              // channels per edge block
#define EGRP (Cn / ECPB)     // 4 channel groups -> partial planes

// Fused blur tiling
#define TILE 16              // output rows per blur block
#define RH (TILE + 6)        // 22 H-pass rows (with +/-3 halo)
#define CPB 4                // channels per blur block
#define CGRP (Cn / CPB)      // 16

// Scratch (__device__ globals; no allocations anywhere)
__device__ float  g_edge_part[(size_t)EGRP * Bn * HWn]; // 4 MB partial channel-sums
__device__ float  g_edge[Bn * HWn];                     // 1 MB summed edge
__device__ float4 g_wts4[(size_t)Bn * HWn];             // 4 MB packed weights (w0,w1,w2,w3)
__device__ unsigned int g_minmax[2 * Bn];               // [0..3]=min bits, [4..7]=max bits

__global__ void init_minmax_kernel() {
    int i = threadIdx.x;
    if (i < Bn) {
        g_minmax[i]      = 0x7f7fffffu;  // +FLT_MAX
        g_minmax[Bn + i] = 0u;           // 0.0f (edge >= 0)
    }
}

// Block = (h_tile, channel_group, b), 256 threads = w.
// Rolling Sobel: 3 LDS per row instead of 9; 8 output-row accumulators per thread.
// Writes a partial (16-channel) sum plane -> deterministic, no float atomics.
__global__ void __launch_bounds__(256) edge_kernel(const float* __restrict__ x) {
    const int w  = threadIdx.x;
    const int h0 = blockIdx.x * TE;
    const int cg = blockIdx.y;
    const int b  = blockIdx.z;

    __shared__ float s[TE + 2][Wn + 2];

    float acc[TE];
#pragma unroll
    for (int j = 0; j < TE; ++j) acc[j] = 0.f;

    const float* xb = x + ((size_t)b * Cn + cg * ECPB) * HWn;

    for (int c = 0; c < ECPB; ++c) {
        const float* plane = xb + (size_t)c * HWn;
        __syncthreads();
#pragma unroll
        for (int r = 0; r < TE + 2; ++r) {
            int hh = h0 - 1 + r;
            s[r][w + 1] = (hh >= 0 && hh < Hn) ? plane[hh * Wn + w] : 0.f;
        }
        if (w == 0) {
#pragma unroll
            for (int r = 0; r < TE + 2; ++r) { s[r][0] = 0.f; s[r][Wn + 1] = 0.f; }
        }
        __syncthreads();

        // Rolling row partials: p = x(w+1)-x(w-1), q = x(w-1)+2x(w)+x(w+1)
        float p0, p1, q0, q1;
        {
            float a = s[0][w], m = s[0][w + 1], e = s[0][w + 2];
            p0 = e - a; q0 = a + 2.f * m + e;
            a = s[1][w]; m = s[1][w + 1]; e = s[1][w + 2];
            p1 = e - a; q1 = a + 2.f * m + e;
        }
#pragma unroll
        for (int rr = 2; rr < TE + 2; ++rr) {
            float a = s[rr][w], m = s[rr][w + 1], e = s[rr][w + 2];
            float p2 = e - a, q2 = a + 2.f * m + e;
            float gx = p0 + 2.f * p1 + p2;   // [1,2,1]_v of [-1,0,1]_h
            float gy = q2 - q0;              // [-1,0,1]_v of [1,2,1]_h
            acc[rr - 2] += gx * gx + gy * gy;
            p0 = p1; p1 = p2; q0 = q1; q1 = q2;
        }
    }

    float* ep = g_edge_part + ((size_t)cg * Bn + b) * HWn + (size_t)h0 * Wn + w;
#pragma unroll
    for (int j = 0; j < TE; ++j)
        ep[(size_t)j * Wn] = acc[j];
}

// Sum the EGRP partial planes -> g_edge, fused per-batch min/max reduce.
__global__ void summinmax_kernel() {
    const int idx = blockIdx.x * 256 + threadIdx.x;  // 0..HW-1
    const int b   = blockIdx.y;

    float e = 0.f;
#pragma unroll
    for (int g = 0; g < EGRP; ++g)
        e += g_edge_part[((size_t)g * Bn + b) * HWn + idx];
    g_edge[b * HWn + idx] = e;

    // min/max of non-negative floats order as uints
    float mn = e, mx = e;
#pragma unroll
    for (int o = 16; o > 0; o >>= 1) {
        mn = fminf(mn, __shfl_xor_sync(0xffffffffu, mn, o));
        mx = fmaxf(mx, __shfl_xor_sync(0xffffffffu, mx, o));
    }
    __shared__ float smn[8], smx[8];
    int lane = threadIdx.x & 31, wid = threadIdx.x >> 5;
    if (lane == 0) { smn[wid] = mn; smx[wid] = mx; }
    __syncthreads();
    if (threadIdx.x == 0) {
        float m1 = smn[0], m2 = smx[0];
#pragma unroll
        for (int i = 1; i < 8; ++i) { m1 = fminf(m1, smn[i]); m2 = fmaxf(m2, smx[i]); }
        atomicMin(&g_minmax[b], __float_as_uint(m1));
        atomicMax(&g_minmax[Bn + b], __float_as_uint(m2));
    }
}

// Per-pixel sigma -> packed float4 of symmetric normalized Gaussian weights.
__global__ void weights_kernel() {
    const int idx = blockIdx.x * 256 + threadIdx.x;
    const int b   = blockIdx.y;

    const float invC = 1.f / (float)Cn;
    float e    = g_edge[b * HWn + idx] * invC;
    float emin = __uint_as_float(g_minmax[b]) * invC;
    float emax = __uint_as_float(g_minmax[Bn + b]) * invC;
    float en   = (e - emin) / (emax + 1e-6f);
    float sig  = 0.6f + 0.6f * en;
    float inv  = 1.f / (2.f * sig * sig);

    float w1 = __expf(-inv);
    float w2 = __expf(-4.f * inv);
    float w3 = __expf(-9.f * inv);
    float r  = 1.f / (1.f + 2.f * (w1 + w2 + w3));

    g_wts4[(size_t)b * HWn + idx] = make_float4(r, w1 * r, w2 * r, w3 * r);
}

// Fused separable blur. Block = (16-row tile, 4-channel group, b), 256 threads = w.
// Per channel: stage 22 x-rows (+/-3 w-halo) -> H-pass into s_h -> V-pass -> out.
// No g_tmp round-trip; weights are a single L1-resident LDG.128 per use.
__global__ void __launch_bounds__(256) blur_kernel(const float* __restrict__ x,
                                                   float* __restrict__ out) {
    const int w  = threadIdx.x;
    const int h0 = blockIdx.x * TILE;
    const int cg = blockIdx.y;
    const int b  = blockIdx.z;

    __shared__ float s_in[RH][Wn + 6];
    __shared__ float s_h[RH][Wn];

    const float4* wp = g_wts4 + (size_t)b * HWn;

    for (int cc = 0; cc < CPB; ++cc) {
        const int c = cg * CPB + cc;
        const float* plane = x + ((size_t)b * Cn + c) * HWn;
        __syncthreads();  // protect smem reuse from previous channel's V-pass
#pragma unroll
        for (int r = 0; r < RH; ++r) {
            int hh = h0 - 3 + r;
            s_in[r][w + 3] = (hh >= 0 && hh < Hn) ? plane[hh * Wn + w] : 0.f;
        }
        if (w < 3) {
#pragma unroll
            for (int r = 0; r < RH; ++r) { s_in[r][w] = 0.f; s_in[r][w + Wn + 3] = 0.f; }
        }
        __syncthreads();

        // Horizontal pass (OOB rows are zero -> H-out 0 regardless of weights; clamp idx)
#pragma unroll
        for (int r = 0; r < RH; ++r) {
            int hcl = min(max(h0 - 3 + r, 0), Hn - 1);
            float4 g = wp[hcl * Wn + w];
            s_h[r][w] = g.x * s_in[r][w + 3]
                      + g.y * (s_in[r][w + 2] + s_in[r][w + 4])
                      + g.z * (s_in[r][w + 1] + s_in[r][w + 5])
                      + g.w * (s_in[r][w]     + s_in[r][w + 6]);
        }
        __syncthreads();

        // Vertical pass + store
        float* op = out + ((size_t)b * Cn + c) * HWn;
#pragma unroll
        for (int i = 0; i < TILE; ++i) {
            float4 g = wp[(h0 + i) * Wn + w];
            const int r = i + 3;
            float v = g.x * s_h[r][w]
                    + g.y * (s_h[r - 1][w] + s_h[r + 1][w])
                    + g.z * (s_h[r - 2][w] + s_h[r + 2][w])
                    + g.w * (s_h[r - 3][w] + s_h[r + 3][w]);
            op[(h0 + i) * Wn + w] = v;
        }
    }
}

extern "C" void kernel_launch(void* const* d_in, const int* in_sizes, int n_in,
                              void* d_out, int out_size) {
    const float* x = (const float*)d_in[0];
    float* out = (float*)d_out;
    (void)in_sizes; (void)n_in; (void)out_size;

    init_minmax_kernel<<<1, 32>>>();
    edge_kernel<<<dim3(Hn / TE, EGRP, Bn), 256>>>(x);
    summinmax_kernel<<<dim3(HWn / 256, Bn), 256>>>();
    weights_kernel<<<dim3(HWn / 256, Bn), 256>>>();
    blur_kernel<<<dim3(Hn / TILE, CGRP, Bn), 256>>>(x, out);
}